// round 11
// baseline (speedup 1.0000x reference)
#include <cuda_runtime.h>
#include <cuda_bf16.h>

// x: [64, 133, 64, 64] fp32 -> out [64, 133, 32, 32]
constexpr int B  = 64;
constexpr int C  = 133;
constexpr int Cm = 128;
constexpr int H  = 64;
constexpr int W  = 64;
constexpr int Ho = 32;
constexpr int Wo = 32;
constexpr int HW = H * W;
constexpr int HoWo = Ho * Wo;

constexpr int NWARPS  = 16;
constexpr int CPW     = Cm / NWARPS;   // 8 pooled channels per warp
constexpr int NTILES  = B * Ho;        // 2048 (b, ho) tiles
constexpr int NBLOCKS = 456;           // 3 per SM (152 SMs), persistent

// Self-resetting work queue: single graph node, deterministic across replays.
__device__ int g_ticket = NBLOCKS;
__device__ int g_done   = 0;

__device__ __forceinline__ float4 ldcs4(const float* p) {
    return __ldcs((const float4*)p);   // streaming: evict-first
}

__global__ __launch_bounds__(NWARPS * 32, 3)
void spatial_maxpool_stats_kernel(const float* __restrict__ x,
                                  float* __restrict__ out) {
    const int lane = threadIdx.x & 31;
    const int warp = threadIdx.x >> 5;
    const int l16  = lane & 15;
    const int half = lane >> 4;

    __shared__ unsigned s_cnt[2][Wo];       // parity double-buffered counts
    __shared__ float4   s_stat[2][5][32];   // [parity][stat chan][row*16 + col4]
    __shared__ int      s_next[2];

    if (threadIdx.x < 64) s_cnt[threadIdx.x >> 5][threadIdx.x & 31] = 0u;
    __syncthreads();

    int tile = blockIdx.x;
    int par  = 0;

    while (tile < NTILES) {
        const int b  = tile >> 5;
        const int ho = tile & 31;
        const float* xb = x   + (size_t)b * C * HW;
        float*       ob = out + (size_t)b * C * HoWo;

        // ---- stat-channel prefetch: warps 0-4 -> smem via cp.async
        if (warp < 5) {
            const float* src = xb + (size_t)(Cm + warp) * HW
                             + (2 * ho + half) * W + 4 * l16;
            unsigned dst = (unsigned)__cvta_generic_to_shared(&s_stat[par][warp][lane]);
            asm volatile("cp.async.cg.shared.global [%0], [%1], 16;\n"
                         "cp.async.commit_group;\n" :: "r"(dst), "l"(src));
        }

        // ---- pooled group 0 loads (4 x LDG.128 per thread, evict-first)
        const int ch0 = warp * CPW + half;
        const float* pc = xb + (size_t)ch0 * HW + (2 * ho) * W + 4 * l16;
        float*       po = ob + (size_t)ch0 * HoWo + ho * Wo + 2 * l16;

        float4 t0[2], u0[2];
#pragma unroll
        for (int k = 0; k < 2; k++) {
            const float* p = pc + (size_t)(2 * k) * HW;
            t0[k] = ldcs4(p);
            u0[k] = ldcs4(p + W);
        }

        // ---- ticket prefetch (published in parity slot; read after the barrier)
        if (threadIdx.x == 0) s_next[par] = atomicAdd(&g_ticket, 1);

        // ---- pooled group 1 loads
        float4 t1[2], u1[2];
#pragma unroll
        for (int k = 0; k < 2; k++) {
            const float* p = pc + (size_t)(4 + 2 * k) * HW;
            t1[k] = ldcs4(p);
            u1[k] = ldcs4(p + W);
        }

        unsigned cnt0 = 0, cnt1 = 0;  // packed 4x8-bit argmax counts
#pragma unroll
        for (int g = 0; g < 2; g++) {
#pragma unroll
            for (int k = 0; k < 2; k++) {
                float4 t = g ? t1[k] : t0[k];
                float4 u = g ? u1[k] : u0[k];
                // window A: (t.x t.y / u.x u.y), B: (t.z t.w / u.z u.w)
                // first-occurrence argmax: later position wins only strictly
                float mtA = fmaxf(t.x, t.y); int itA = (t.y > t.x) ? 1 : 0;
                float mbA = fmaxf(u.x, u.y); int ibA = (u.y > u.x) ? 3 : 2;
                float mA  = fmaxf(mtA, mbA); int iA  = (mbA > mtA) ? ibA : itA;

                float mtB = fmaxf(t.z, t.w); int itB = (t.w > t.z) ? 1 : 0;
                float mbB = fmaxf(u.z, u.w); int ibB = (u.w > u.z) ? 3 : 2;
                float mB  = fmaxf(mtB, mbB); int iB  = (mbB > mtB) ? ibB : itB;

                float2 st; st.x = mA; st.y = mB;
                *(float2*)(po + (size_t)(g * 4 + 2 * k) * HoWo) = st;
                cnt0 += 1u << (8 * iA);
                cnt1 += 1u << (8 * iB);
            }
        }
        atomicAdd(&s_cnt[par][2 * l16],     cnt0);
        atomicAdd(&s_cnt[par][2 * l16 + 1], cnt1);

        asm volatile("cp.async.wait_group 0;" ::: "memory");
        __syncthreads();   // single per-tile barrier: counts/stats/ticket published

        const int next_tile = s_next[par];

        // ---- distributed epilogue: warp j (0-4) computes stat channel j.
        // All 5 recompute the means locally; only the owning warp stores.
        if (warp < 5) {
            const int wo = lane;
            const unsigned cc = s_cnt[par][wo];

            const float inv = 1.0f / (float)Cm;
            const float w0 = (float)( cc        & 255u) * inv;
            const float w1 = (float)((cc >>  8) & 255u) * inv;
            const float w2 = (float)((cc >> 16) & 255u) * inv;
            const float w3 = (float)((cc >> 24) & 255u) * inv;

            const int e = wo & 1;             // element pair within float4
            // mu channels (0,1) needed by everyone
            float4 a0 = s_stat[par][0][wo >> 1], c0 = s_stat[par][0][16 + (wo >> 1)];
            float4 a1 = s_stat[par][1][wo >> 1], c1 = s_stat[par][1][16 + (wo >> 1)];
            const float m00 = e ? a0.z : a0.x, m01 = e ? a0.w : a0.y;
            const float m02 = e ? c0.z : c0.x, m03 = e ? c0.w : c0.y;
            const float m10 = e ? a1.z : a1.x, m11 = e ? a1.w : a1.y;
            const float m12 = e ? c1.z : c1.x, m13 = e ? c1.w : c1.y;

            const float mean0 = m00*w0 + m01*w1 + m02*w2 + m03*w3;
            const float mean1 = m10*w0 + m11*w1 + m12*w2 + m13*w3;

            float res;
            if (warp == 0) {
                res = mean0;
            } else if (warp == 1) {
                res = mean1;
            } else {
                float4 aj = s_stat[par][warp][wo >> 1];
                float4 cj = s_stat[par][warp][16 + (wo >> 1)];
                const float sj0 = e ? aj.z : aj.x, sj1 = e ? aj.w : aj.y;
                const float sj2 = e ? cj.z : cj.x, sj3 = e ? cj.w : cj.y;
                res = sj0*w0 + sj1*w1 + sj2*w2 + sj3*w3;

                const float d00 = m00-mean0, d10 = m01-mean0, d20 = m02-mean0, d30 = m03-mean0;
                const float d01 = m10-mean1, d11 = m11-mean1, d21 = m12-mean1, d31 = m13-mean1;
                if (warp == 2)      res += d00*d00*w0 + d10*d10*w1 + d20*d20*w2 + d30*d30*w3;
                else if (warp == 3) res += d01*d01*w0 + d11*d11*w1 + d21*d21*w2 + d31*d31*w3;
                else                res += d00*d01*w0 + d10*d11*w1 + d20*d21*w2 + d30*d31*w3;
            }
            ob[(size_t)(Cm + warp) * HoWo + ho * Wo + wo] = res;

            // all 5 epilogue warps have read s_cnt[par]; then warp 0 re-zeroes it.
            asm volatile("bar.sync 1, 160;" ::: "memory");
            if (warp == 0) s_cnt[par][wo] = 0u;
            // buffer reused 2 tiles later; intervening block barrier orders it.
        }

        tile = next_tile;
        par ^= 1;
    }

    // ---- self-reset for the next graph replay (last block restores state)
    if (threadIdx.x == 0) {
        __threadfence();                          // order prior atomics/stores
        int d = atomicAdd(&g_done, 1);
        if (d == NBLOCKS - 1) {
            g_ticket = NBLOCKS;
            g_done   = 0;
        }
    }
}

extern "C" void kernel_launch(void* const* d_in, const int* in_sizes, int n_in,
                              void* d_out, int out_size) {
    const float* x = (const float*)d_in[0];
    float* out = (float*)d_out;
    spatial_maxpool_stats_kernel<<<NBLOCKS, NWARPS * 32>>>(x, out);
}